// round 11
// baseline (speedup 1.0000x reference)
#include <cuda_runtime.h>
#include <cuda_bf16.h>
#include <cstdint>

// ---------------------------------------------------------------------------
// y = x @ Mf + cf  (exact collapse of the 9-layer linear chain), main pass on
// tensor cores via mma.sync.m16n8k8 tf32 (sm_80+ PTX -> HMMA on sm_103).
//  - warp tile: 16 rows x 16 cols(j; 10 used) x K=784 (98 k-steps of 8)
//  - x staged warp-privately via cp.async (R9-proven machinery), pitch 36
//  - Mf pre-rounded to tf32 (cvt.rna) at collapse; A rounded at load
//  - D accumulated in 8 fp32 regs/lane; bias added in fp32 at store
// ---------------------------------------------------------------------------

#define BSZ     65536
#define KDIM    784
#define NOUT    10
#define CTPB    256
#define MTPB    256               // 8 warps
#define WROWS   16                // rows per warp
#define ROWS_PER_BLOCK 128        // 8 warps * 16
#define NCH     25                // 24 full 32-k chunks + 16-k tail
#define XP      36                // stage pitch (floats): banks (4g+tig) -> conflict-free
#define STGF    (WROWS * XP)      // 576 floats per warp-stage buffer

// dynamic smem (floats): [0,7840) B  [7840,7850) cfs  [7856, +8*2*576) stages
#define SM_B      0
#define SM_CF     7840
#define SM_STG    7856
#define SM_TOTALF (SM_STG + 8 * 2 * STGF)    // 7856 + 9216 = 17072 floats

typedef unsigned long long u64;

__device__ float g_Mf[KDIM * NOUT];   // tf32-rounded collapsed matrix [k][j]
__device__ float g_cf[NOUT];          // fp32 collapsed bias

// ---- helpers ---------------------------------------------------------------
__device__ __forceinline__ uint32_t cvt_tf32(float f) {
    uint32_t u;
    asm("cvt.rna.tf32.f32 %0, %1;" : "=r"(u) : "f"(f));
    return u;
}
__device__ __forceinline__ void mma_tf32(float& d0, float& d1, float& d2, float& d3,
                                         uint32_t a0, uint32_t a1, uint32_t a2, uint32_t a3,
                                         uint32_t b0, uint32_t b1) {
    asm volatile(
        "mma.sync.aligned.m16n8k8.row.col.f32.tf32.tf32.f32 "
        "{%0,%1,%2,%3}, {%4,%5,%6,%7}, {%8,%9}, {%0,%1,%2,%3};"
        : "+f"(d0), "+f"(d1), "+f"(d2), "+f"(d3)
        : "r"(a0), "r"(a1), "r"(a2), "r"(a3), "r"(b0), "r"(b1));
}
__device__ __forceinline__ void cp16(unsigned dst, const float* src) {
    asm volatile("cp.async.cg.shared.global [%0], [%1], 16;" :: "r"(dst), "l"(src));
}
#define CP_COMMIT() asm volatile("cp.async.commit_group;" ::: "memory")
#define CP_WAIT1()  asm volatile("cp.async.wait_group 1;" ::: "memory")

// ---------------------------------------------------------------------------
// collapse_all: 31 blocks x 256 (R7-proven), now tf32-rounding Mf on store.
// ---------------------------------------------------------------------------
#define SW1   0
#define SW2   2144
#define SW3   2464
#define SB0   3072
#define SB1   3152
#define SBS   3184
#define SWTOT 3264

__global__ void collapse_all(const float* __restrict__ W0, const float* __restrict__ b0,
                             const float* __restrict__ W1, const float* __restrict__ b1,
                             const float* __restrict__ W2, const float* __restrict__ b2,
                             const float* __restrict__ W3, const float* __restrict__ b3,
                             const float* __restrict__ W4, const float* __restrict__ b4,
                             const float* __restrict__ W5, const float* __restrict__ b5,
                             const float* __restrict__ W6, const float* __restrict__ b6,
                             const float* __restrict__ W7, const float* __restrict__ b7,
                             const float* __restrict__ W8, const float* __restrict__ b8) {
    __shared__ float sw[SWTOT];
    __shared__ float R[2][100];
    __shared__ float Q[31 * 10];
    __shared__ float S[69 * 10];
    __shared__ float c1s[31];
    __shared__ float cs[2][10];
    const int t = threadIdx.x;

    for (int i = t; i < 2139; i += CTPB) sw[SW1 + i] = W1[i];
    for (int i = t; i < 310;  i += CTPB) sw[SW2 + i] = W2[i];
    {   const float* Wsrc[6] = {W3, W4, W5, W6, W7, W8};
        for (int i = t; i < 600; i += CTPB) sw[SW3 + i] = Wsrc[i / 100][i % 100];
    }
    if (t < 69)  sw[SB0 + t] = b0[t];
    if (t < 31)  sw[SB1 + t] = b1[t];
    {   const float* bsrc[7] = {b2, b3, b4, b5, b6, b7, b8};
        if (t < 70) sw[SBS + t] = bsrc[t / 10][t % 10];
    }
    __syncthreads();

    if (t < 100) R[0][t] = sw[SW3 + (t % 10) * 10 + (t / 10)];
    __syncthreads();
    int cur = 0;
    #pragma unroll 1
    for (int l = 1; l < 6; ++l) {
        int nxt = cur ^ 1;
        if (t < 100) {
            int k = t / 10, j = t % 10;
            float s = 0.f;
            #pragma unroll
            for (int m = 0; m < 10; ++m)
                s = fmaf(R[cur][k * 10 + m], sw[SW3 + l * 100 + j * 10 + m], s);
            R[nxt][t] = s;
        }
        __syncthreads();
        cur = nxt;
    }

    for (int e = t; e < 310; e += CTPB) {
        int k = e / 10, j = e % 10;
        float s = 0.f;
        #pragma unroll
        for (int m = 0; m < 10; ++m)
            s = fmaf(sw[SW2 + m * 31 + k], R[cur][m * 10 + j], s);
        Q[e] = s;
    }
    __syncthreads();

    for (int e = t; e < 690; e += CTPB) {
        int k = e / 10, j = e % 10;
        float s0 = 0.f, s1 = 0.f, s2 = 0.f, s3 = 0.f;
        #pragma unroll
        for (int m = 0; m < 28; m += 4) {
            s0 = fmaf(sw[SW1 + (m + 0) * 69 + k], Q[(m + 0) * 10 + j], s0);
            s1 = fmaf(sw[SW1 + (m + 1) * 69 + k], Q[(m + 1) * 10 + j], s1);
            s2 = fmaf(sw[SW1 + (m + 2) * 69 + k], Q[(m + 2) * 10 + j], s2);
            s3 = fmaf(sw[SW1 + (m + 3) * 69 + k], Q[(m + 3) * 10 + j], s3);
        }
        #pragma unroll
        for (int m = 28; m < 31; ++m)
            s0 = fmaf(sw[SW1 + m * 69 + k], Q[m * 10 + j], s0);
        S[e] = (s0 + s1) + (s2 + s3);
    }
    __syncthreads();

    {
        int e = blockIdx.x * CTPB + t;
        if (e < KDIM * NOUT) {
            int j = e / KDIM, i = e % KDIM;
            float s0 = 0.f, s1 = 0.f, s2 = 0.f, s3 = 0.f;
            #pragma unroll
            for (int k = 0; k < 68; k += 4) {
                s0 = fmaf(W0[(k + 0) * KDIM + i], S[(k + 0) * 10 + j], s0);
                s1 = fmaf(W0[(k + 1) * KDIM + i], S[(k + 1) * 10 + j], s1);
                s2 = fmaf(W0[(k + 2) * KDIM + i], S[(k + 2) * 10 + j], s2);
                s3 = fmaf(W0[(k + 3) * KDIM + i], S[(k + 3) * 10 + j], s3);
            }
            s0 = fmaf(W0[68 * KDIM + i], S[68 * 10 + j], s0);
            float v = (s0 + s1) + (s2 + s3);
            g_Mf[i * 10 + j] = __uint_as_float(cvt_tf32(v));   // pre-round to tf32
        }
    }

    if (blockIdx.x == 0) {
        if (t < 31) {
            float s = sw[SB1 + t];
            for (int k = 0; k < 69; ++k)
                s = fmaf(sw[SB0 + k], sw[SW1 + t * 69 + k], s);
            c1s[t] = s;
        }
        __syncthreads();
        if (t < 10) {
            float s = sw[SBS + t];
            for (int m = 0; m < 31; ++m)
                s = fmaf(c1s[m], sw[SW2 + t * 31 + m], s);
            cs[0][t] = s;
        }
        __syncthreads();
        int cb = 0;
        #pragma unroll 1
        for (int l = 0; l < 6; ++l) {
            int nb = cb ^ 1;
            if (t < 10) {
                float s = sw[SBS + (l + 1) * 10 + t];
                #pragma unroll
                for (int m = 0; m < 10; ++m)
                    s = fmaf(cs[cb][m], sw[SW3 + l * 100 + t * 10 + m], s);
                cs[nb][t] = s;
            }
            __syncthreads();
            cb = nb;
        }
        if (t < 10) g_cf[t] = cs[cb][t];
    }
}

// ---------------------------------------------------------------------------
// mlp_mma: out[65536,10] = x @ Mf + cf via m16n8k8 tf32 mma.sync.
//  warp w handles rows [wrow, wrow+16); n covered by two 8-wide halves.
//  x staged via cp.async into warp-private double buffer (32-k chunks).
// ---------------------------------------------------------------------------
__global__ __launch_bounds__(MTPB, 3)
void mlp_mma(const float* __restrict__ x, float* __restrict__ out) {
    extern __shared__ float sm[];
    float* Bs  = sm + SM_B;     // Mf (tf32 bits) [k][10]
    float* cfs = sm + SM_CF;

    const int t    = threadIdx.x;
    const int lane = t & 31;
    const int warp = t >> 5;
    const int g    = lane >> 2;     // 0..7  (row group / n index)
    const int tig  = lane & 3;      // 0..3  (k index within half)

    float* stg[2];
    stg[0] = sm + SM_STG + (warp * 2 + 0) * STGF;
    stg[1] = sm + SM_STG + (warp * 2 + 1) * STGF;
    unsigned stg_u32[2];
    stg_u32[0] = (unsigned)__cvta_generic_to_shared(stg[0]);
    stg_u32[1] = (unsigned)__cvta_generic_to_shared(stg[1]);

    const int wrow = blockIdx.x * ROWS_PER_BLOCK + warp * WROWS;
    const float* xw = x + (size_t)wrow * KDIM;

    // ---- stage chunk 0 (overlaps B fill) ----
    #pragma unroll
    for (int i = 0; i < 4; ++i) {
        int f4 = lane + 32 * i;                 // 0..127 granules of 16B
        int row = f4 >> 3, col = (f4 & 7) << 2;
        cp16(stg_u32[0] + (row * XP + col) * 4, xw + row * KDIM + col);
    }
    CP_COMMIT();

    // ---- fill B + bias (coalesced) ----
    for (int i = t; i < KDIM * NOUT; i += MTPB) Bs[i] = g_Mf[i];
    if (t < NOUT) cfs[t] = g_cf[t];
    __syncthreads();

    float d0[4] = {0.f, 0.f, 0.f, 0.f};   // n-half 0: j 0..7
    float d1[4] = {0.f, 0.f, 0.f, 0.f};   // n-half 1: j 8..15 (8,9 used)

    #pragma unroll 1
    for (int ch = 0; ch < NCH; ++ch) {
        // prefetch next chunk into the other buffer
        if (ch < NCH - 2) {                       // next is a full 32-k chunk
            unsigned d = stg_u32[(ch + 1) & 1];
            const float* gsrc = xw + (ch + 1) * 32;
            #pragma unroll
            for (int i = 0; i < 4; ++i) {
                int f4 = lane + 32 * i;
                int row = f4 >> 3, col = (f4 & 7) << 2;
                cp16(d + (row * XP + col) * 4, gsrc + row * KDIM + col);
            }
        } else if (ch == NCH - 2) {               // next is the 16-k tail
            unsigned d = stg_u32[(ch + 1) & 1];
            const float* gsrc = xw + (NCH - 1) * 32;
            #pragma unroll
            for (int i = 0; i < 2; ++i) {
                int f4 = lane + 32 * i;           // 0..63
                int row = f4 >> 2, col = (f4 & 3) << 2;
                cp16(d + (row * XP + col) * 4, gsrc + row * KDIM + col);
            }
        }
        CP_COMMIT();
        CP_WAIT1();                               // chunk ch resident
        __syncwarp();

        const float* xs = stg[ch & 1];
        const int nsteps = (ch == NCH - 1) ? 2 : 4;
        #pragma unroll
        for (int st = 0; st < 4; ++st) {
            if (st >= nsteps) break;
            const int kl = st * 8;                // k offset within chunk
            const int kg = ch * 32 + kl;          // global k

            // A fragment (rows g, g+8; cols tig, tig+4), rounded to tf32
            uint32_t a0 = cvt_tf32(xs[(g    ) * XP + kl + tig    ]);
            uint32_t a1 = cvt_tf32(xs[(g + 8) * XP + kl + tig    ]);
            uint32_t a2 = cvt_tf32(xs[(g    ) * XP + kl + tig + 4]);
            uint32_t a3 = cvt_tf32(xs[(g + 8) * XP + kl + tig + 4]);

            // B fragments (pre-rounded): b(k, n) = Bs[k*10 + n]
            uint32_t b00 = __float_as_uint(Bs[(kg + tig    ) * 10 + g]);
            uint32_t b01 = __float_as_uint(Bs[(kg + tig + 4) * 10 + g]);
            mma_tf32(d0[0], d0[1], d0[2], d0[3], a0, a1, a2, a3, b00, b01);

            uint32_t b10 = (g < 2) ? __float_as_uint(Bs[(kg + tig    ) * 10 + 8 + g]) : 0u;
            uint32_t b11 = (g < 2) ? __float_as_uint(Bs[(kg + tig + 4) * 10 + 8 + g]) : 0u;
            mma_tf32(d1[0], d1[1], d1[2], d1[3], a0, a1, a2, a3, b10, b11);
        }
        __syncwarp();                             // buffer reuse fence
    }

    // ---- epilogue: D layout c0,c1 -> (row g, cols 2tig,2tig+1); c2,c3 -> row g+8
    {
        const int j0 = 2 * tig;
        float2 v;
        float* opA = out + (size_t)(wrow + g) * NOUT;
        float* opB = out + (size_t)(wrow + g + 8) * NOUT;
        v.x = d0[0] + cfs[j0];     v.y = d0[1] + cfs[j0 + 1];
        *(float2*)(opA + j0) = v;
        v.x = d0[2] + cfs[j0];     v.y = d0[3] + cfs[j0 + 1];
        *(float2*)(opB + j0) = v;
        if (tig == 0) {                            // n-half 1: j = 8,9
            v.x = d1[0] + cfs[8];  v.y = d1[1] + cfs[9];
            *(float2*)(opA + 8) = v;
            v.x = d1[2] + cfs[8];  v.y = d1[3] + cfs[9];
            *(float2*)(opB + 8) = v;
        }
    }
}

// ---------------------------------------------------------------------------
extern "C" void kernel_launch(void* const* d_in, const int* in_sizes, int n_in,
                              void* d_out, int out_size) {
    const float* x  = (const float*)d_in[0];
    const float* W0 = (const float*)d_in[1];
    const float* b0 = (const float*)d_in[2];
    const float* W1 = (const float*)d_in[3];
    const float* b1 = (const float*)d_in[4];
    const float* W2 = (const float*)d_in[5];
    const float* b2 = (const float*)d_in[6];
    const float* W3 = (const float*)d_in[7];
    const float* b3 = (const float*)d_in[8];
    const float* W4 = (const float*)d_in[9];
    const float* b4 = (const float*)d_in[10];
    const float* W5 = (const float*)d_in[11];
    const float* b5 = (const float*)d_in[12];
    const float* W6 = (const float*)d_in[13];
    const float* b6 = (const float*)d_in[14];
    const float* W7 = (const float*)d_in[15];
    const float* b7 = (const float*)d_in[16];
    const float* W8 = (const float*)d_in[17];
    const float* b8 = (const float*)d_in[18];
    float* out = (float*)d_out;

    static bool attr_set = false;
    const int smem_bytes = SM_TOTALF * sizeof(float);    // 68288 B
    if (!attr_set) {
        cudaFuncSetAttribute(mlp_mma, cudaFuncAttributeMaxDynamicSharedMemorySize,
                             smem_bytes);
        attr_set = true;
    }

    collapse_all<<<(KDIM * NOUT + CTPB - 1) / CTPB, CTPB>>>(
        W0, b0, W1, b1, W2, b2, W3, b3, W4, b4,
        W5, b5, W6, b6, W7, b7, W8, b8);

    mlp_mma<<<BSZ / ROWS_PER_BLOCK, MTPB, smem_bytes>>>(x, out);   // 512 blocks
}

// round 12
// speedup vs baseline: 1.2479x; 1.2479x over previous
#include <cuda_runtime.h>
#include <cuda_bf16.h>
#include <cstdint>

// ---------------------------------------------------------------------------
// y = x @ Mf + cf  (exact collapse of the 9-layer linear chain), main pass on
// tensor cores via mma.sync.m16n8k8 tf32 (sm_80+ PTX -> HMMA on sm_103).
// R12: 64-k staged chunks (double compute-per-wait, 8KB in flight per warp)
// to convert the latency-bound R11 mainloop into a DRAM-bound one.
// ---------------------------------------------------------------------------

#define BSZ     65536
#define KDIM    784
#define NOUT    10
#define CTPB    256
#define MTPB    256               // 8 warps
#define WROWS   16                // rows per warp
#define ROWS_PER_BLOCK 128        // 8 warps * 16
#define NCH     13                // 12 full 64-k chunks + 16-k tail
#define XP      68                // stage pitch: bank=(4g+tig+kl)%32 -> conflict-free
#define STGF    (WROWS * XP)      // 1088 floats per warp-stage buffer

// dynamic smem (floats)
#define SM_B      0               // 7840: Mf (tf32 bits) [k][10]
#define SM_CF     7840            // 10: bias
#define SM_STG    7856
#define SM_TOTALF (SM_STG + 8 * 2 * STGF)    // 7856 + 17408 = 25264 (101 KB)

typedef unsigned long long u64;

__device__ float g_Mf[KDIM * NOUT];   // tf32-rounded collapsed matrix [k][j]
__device__ float g_cf[NOUT];          // fp32 collapsed bias

// ---- helpers ---------------------------------------------------------------
__device__ __forceinline__ uint32_t cvt_tf32(float f) {
    uint32_t u;
    asm("cvt.rna.tf32.f32 %0, %1;" : "=r"(u) : "f"(f));
    return u;
}
__device__ __forceinline__ void mma_tf32(float& d0, float& d1, float& d2, float& d3,
                                         uint32_t a0, uint32_t a1, uint32_t a2, uint32_t a3,
                                         uint32_t b0, uint32_t b1) {
    asm volatile(
        "mma.sync.aligned.m16n8k8.row.col.f32.tf32.tf32.f32 "
        "{%0,%1,%2,%3}, {%4,%5,%6,%7}, {%8,%9}, {%0,%1,%2,%3};"
        : "+f"(d0), "+f"(d1), "+f"(d2), "+f"(d3)
        : "r"(a0), "r"(a1), "r"(a2), "r"(a3), "r"(b0), "r"(b1));
}
__device__ __forceinline__ void cp16(unsigned dst, const float* src) {
    asm volatile("cp.async.cg.shared.global [%0], [%1], 16;" :: "r"(dst), "l"(src));
}
#define CP_COMMIT() asm volatile("cp.async.commit_group;" ::: "memory")
#define CP_WAIT1()  asm volatile("cp.async.wait_group 1;" ::: "memory")

// ---------------------------------------------------------------------------
// collapse_all: 31 blocks x 256 (R11-proven), tf32-rounds Mf on store.
// ---------------------------------------------------------------------------
#define SW1   0
#define SW2   2144
#define SW3   2464
#define SB0   3072
#define SB1   3152
#define SBS   3184
#define SWTOT 3264

__global__ void collapse_all(const float* __restrict__ W0, const float* __restrict__ b0,
                             const float* __restrict__ W1, const float* __restrict__ b1,
                             const float* __restrict__ W2, const float* __restrict__ b2,
                             const float* __restrict__ W3, const float* __restrict__ b3,
                             const float* __restrict__ W4, const float* __restrict__ b4,
                             const float* __restrict__ W5, const float* __restrict__ b5,
                             const float* __restrict__ W6, const float* __restrict__ b6,
                             const float* __restrict__ W7, const float* __restrict__ b7,
                             const float* __restrict__ W8, const float* __restrict__ b8) {
    __shared__ float sw[SWTOT];
    __shared__ float R[2][100];
    __shared__ float Q[31 * 10];
    __shared__ float S[69 * 10];
    __shared__ float c1s[31];
    __shared__ float cs[2][10];
    const int t = threadIdx.x;

    for (int i = t; i < 2139; i += CTPB) sw[SW1 + i] = W1[i];
    for (int i = t; i < 310;  i += CTPB) sw[SW2 + i] = W2[i];
    {   const float* Wsrc[6] = {W3, W4, W5, W6, W7, W8};
        for (int i = t; i < 600; i += CTPB) sw[SW3 + i] = Wsrc[i / 100][i % 100];
    }
    if (t < 69)  sw[SB0 + t] = b0[t];
    if (t < 31)  sw[SB1 + t] = b1[t];
    {   const float* bsrc[7] = {b2, b3, b4, b5, b6, b7, b8};
        if (t < 70) sw[SBS + t] = bsrc[t / 10][t % 10];
    }
    __syncthreads();

    if (t < 100) R[0][t] = sw[SW3 + (t % 10) * 10 + (t / 10)];
    __syncthreads();
    int cur = 0;
    #pragma unroll 1
    for (int l = 1; l < 6; ++l) {
        int nxt = cur ^ 1;
        if (t < 100) {
            int k = t / 10, j = t % 10;
            float s = 0.f;
            #pragma unroll
            for (int m = 0; m < 10; ++m)
                s = fmaf(R[cur][k * 10 + m], sw[SW3 + l * 100 + j * 10 + m], s);
            R[nxt][t] = s;
        }
        __syncthreads();
        cur = nxt;
    }

    for (int e = t; e < 310; e += CTPB) {
        int k = e / 10, j = e % 10;
        float s = 0.f;
        #pragma unroll
        for (int m = 0; m < 10; ++m)
            s = fmaf(sw[SW2 + m * 31 + k], R[cur][m * 10 + j], s);
        Q[e] = s;
    }
    __syncthreads();

    for (int e = t; e < 690; e += CTPB) {
        int k = e / 10, j = e % 10;
        float s0 = 0.f, s1 = 0.f, s2 = 0.f, s3 = 0.f;
        #pragma unroll
        for (int m = 0; m < 28; m += 4) {
            s0 = fmaf(sw[SW1 + (m + 0) * 69 + k], Q[(m + 0) * 10 + j], s0);
            s1 = fmaf(sw[SW1 + (m + 1) * 69 + k], Q[(m + 1) * 10 + j], s1);
            s2 = fmaf(sw[SW1 + (m + 2) * 69 + k], Q[(m + 2) * 10 + j], s2);
            s3 = fmaf(sw[SW1 + (m + 3) * 69 + k], Q[(m + 3) * 10 + j], s3);
        }
        #pragma unroll
        for (int m = 28; m < 31; ++m)
            s0 = fmaf(sw[SW1 + m * 69 + k], Q[m * 10 + j], s0);
        S[e] = (s0 + s1) + (s2 + s3);
    }
    __syncthreads();

    {
        int e = blockIdx.x * CTPB + t;
        if (e < KDIM * NOUT) {
            int j = e / KDIM, i = e % KDIM;
            float s0 = 0.f, s1 = 0.f, s2 = 0.f, s3 = 0.f;
            #pragma unroll
            for (int k = 0; k < 68; k += 4) {
                s0 = fmaf(W0[(k + 0) * KDIM + i], S[(k + 0) * 10 + j], s0);
                s1 = fmaf(W0[(k + 1) * KDIM + i], S[(k + 1) * 10 + j], s1);
                s2 = fmaf(W0[(k + 2) * KDIM + i], S[(k + 2) * 10 + j], s2);
                s3 = fmaf(W0[(k + 3) * KDIM + i], S[(k + 3) * 10 + j], s3);
            }
            s0 = fmaf(W0[68 * KDIM + i], S[68 * 10 + j], s0);
            float v = (s0 + s1) + (s2 + s3);
            g_Mf[i * 10 + j] = __uint_as_float(cvt_tf32(v));   // pre-round to tf32
        }
    }

    if (blockIdx.x == 0) {
        if (t < 31) {
            float s = sw[SB1 + t];
            for (int k = 0; k < 69; ++k)
                s = fmaf(sw[SB0 + k], sw[SW1 + t * 69 + k], s);
            c1s[t] = s;
        }
        __syncthreads();
        if (t < 10) {
            float s = sw[SBS + t];
            for (int m = 0; m < 31; ++m)
                s = fmaf(c1s[m], sw[SW2 + t * 31 + m], s);
            cs[0][t] = s;
        }
        __syncthreads();
        int cb = 0;
        #pragma unroll 1
        for (int l = 0; l < 6; ++l) {
            int nb = cb ^ 1;
            if (t < 10) {
                float s = sw[SBS + (l + 1) * 10 + t];
                #pragma unroll
                for (int m = 0; m < 10; ++m)
                    s = fmaf(cs[cb][m], sw[SW3 + l * 100 + t * 10 + m], s);
                cs[nb][t] = s;
            }
            __syncthreads();
            cb = nb;
        }
        if (t < 10) g_cf[t] = cs[cb][t];
    }
}

// ---------------------------------------------------------------------------
// mlp_mma: out = x @ Mf + cf via m16n8k8 tf32 mma.sync, 64-k staged chunks.
// ---------------------------------------------------------------------------
__global__ __launch_bounds__(MTPB, 2)
void mlp_mma(const float* __restrict__ x, float* __restrict__ out) {
    extern __shared__ float sm[];
    float* Bs  = sm + SM_B;
    float* cfs = sm + SM_CF;

    const int t    = threadIdx.x;
    const int lane = t & 31;
    const int warp = t >> 5;
    const int g    = lane >> 2;     // 0..7
    const int tig  = lane & 3;      // 0..3

    float* stg[2];
    stg[0] = sm + SM_STG + (warp * 2 + 0) * STGF;
    stg[1] = sm + SM_STG + (warp * 2 + 1) * STGF;
    unsigned stg_u32[2];
    stg_u32[0] = (unsigned)__cvta_generic_to_shared(stg[0]);
    stg_u32[1] = (unsigned)__cvta_generic_to_shared(stg[1]);

    const int wrow = blockIdx.x * ROWS_PER_BLOCK + warp * WROWS;
    const float* xw = x + (size_t)wrow * KDIM;

    // ---- stage chunk 0 (16 rows x 64 floats, 8 granule-rounds) ----
    #pragma unroll
    for (int i = 0; i < 8; ++i) {
        int f4 = lane + 32 * i;                 // 0..255 granules of 16B
        int row = f4 >> 4, col = (f4 & 15) << 2;
        cp16(stg_u32[0] + (row * XP + col) * 4, xw + row * KDIM + col);
    }
    CP_COMMIT();

    // ---- fill B + bias (coalesced) ----
    for (int i = t; i < KDIM * NOUT; i += MTPB) Bs[i] = g_Mf[i];
    if (t < NOUT) cfs[t] = g_cf[t];
    __syncthreads();

    float d0[4] = {0.f, 0.f, 0.f, 0.f};   // j 0..7
    float d1[4] = {0.f, 0.f, 0.f, 0.f};   // j 8..15 (8,9 used)

    #pragma unroll 1
    for (int ch = 0; ch < NCH; ++ch) {
        // prefetch next chunk into the other buffer
        if (ch < NCH - 2) {                       // next is a full 64-k chunk
            unsigned d = stg_u32[(ch + 1) & 1];
            const float* gsrc = xw + (ch + 1) * 64;
            #pragma unroll
            for (int i = 0; i < 8; ++i) {
                int f4 = lane + 32 * i;
                int row = f4 >> 4, col = (f4 & 15) << 2;
                cp16(d + (row * XP + col) * 4, gsrc + row * KDIM + col);
            }
        } else if (ch == NCH - 2) {               // next is the 16-k tail
            unsigned d = stg_u32[(ch + 1) & 1];
            const float* gsrc = xw + (NCH - 1) * 64;   // k = 768
            #pragma unroll
            for (int i = 0; i < 2; ++i) {
                int f4 = lane + 32 * i;           // 0..63
                int row = f4 >> 2, col = (f4 & 3) << 2;
                cp16(d + (row * XP + col) * 4, gsrc + row * KDIM + col);
            }
        }
        CP_COMMIT();                              // (empty group at ch==NCH-1)
        CP_WAIT1();                               // chunk ch resident
        __syncwarp();

        const float* xs = stg[ch & 1];
        const int nsteps = (ch == NCH - 1) ? 2 : 8;
        #pragma unroll
        for (int st = 0; st < 8; ++st) {
            if (st >= nsteps) break;
            const int kl = st * 8;                // k offset within chunk
            const int kg = ch * 64 + kl;          // global k

            uint32_t a0 = cvt_tf32(xs[(g    ) * XP + kl + tig    ]);
            uint32_t a1 = cvt_tf32(xs[(g + 8) * XP + kl + tig    ]);
            uint32_t a2 = cvt_tf32(xs[(g    ) * XP + kl + tig + 4]);
            uint32_t a3 = cvt_tf32(xs[(g + 8) * XP + kl + tig + 4]);

            uint32_t b00 = __float_as_uint(Bs[(kg + tig    ) * 10 + g]);
            uint32_t b01 = __float_as_uint(Bs[(kg + tig + 4) * 10 + g]);
            mma_tf32(d0[0], d0[1], d0[2], d0[3], a0, a1, a2, a3, b00, b01);

            uint32_t b10 = (g < 2) ? __float_as_uint(Bs[(kg + tig    ) * 10 + 8 + g]) : 0u;
            uint32_t b11 = (g < 2) ? __float_as_uint(Bs[(kg + tig + 4) * 10 + 8 + g]) : 0u;
            mma_tf32(d1[0], d1[1], d1[2], d1[3], a0, a1, a2, a3, b10, b11);
        }
        __syncwarp();                             // buffer reuse fence
    }

    // ---- epilogue: D c0,c1 -> (row g, cols 2tig,2tig+1); c2,c3 -> row g+8 ----
    {
        const int j0 = 2 * tig;
        float2 v;
        float* opA = out + (size_t)(wrow + g) * NOUT;
        float* opB = out + (size_t)(wrow + g + 8) * NOUT;
        v.x = d0[0] + cfs[j0];     v.y = d0[1] + cfs[j0 + 1];
        *(float2*)(opA + j0) = v;
        v.x = d0[2] + cfs[j0];     v.y = d0[3] + cfs[j0 + 1];
        *(float2*)(opB + j0) = v;
        if (tig == 0) {                            // j = 8,9
            v.x = d1[0] + cfs[8];  v.y = d1[1] + cfs[9];
            *(float2*)(opA + 8) = v;
            v.x = d1[2] + cfs[8];  v.y = d1[3] + cfs[9];
            *(float2*)(opB + 8) = v;
        }
    }
}

// ---------------------------------------------------------------------------
extern "C" void kernel_launch(void* const* d_in, const int* in_sizes, int n_in,
                              void* d_out, int out_size) {
    const float* x  = (const float*)d_in[0];
    const float* W0 = (const float*)d_in[1];
    const float* b0 = (const float*)d_in[2];
    const float* W1 = (const float*)d_in[3];
    const float* b1 = (const float*)d_in[4];
    const float* W2 = (const float*)d_in[5];
    const float* b2 = (const float*)d_in[6];
    const float* W3 = (const float*)d_in[7];
    const float* b3 = (const float*)d_in[8];
    const float* W4 = (const float*)d_in[9];
    const float* b4 = (const float*)d_in[10];
    const float* W5 = (const float*)d_in[11];
    const float* b5 = (const float*)d_in[12];
    const float* W6 = (const float*)d_in[13];
    const float* b6 = (const float*)d_in[14];
    const float* W7 = (const float*)d_in[15];
    const float* b7 = (const float*)d_in[16];
    const float* W8 = (const float*)d_in[17];
    const float* b8 = (const float*)d_in[18];
    float* out = (float*)d_out;

    static bool attr_set = false;
    const int smem_bytes = SM_TOTALF * sizeof(float);    // 101056 B
    if (!attr_set) {
        cudaFuncSetAttribute(mlp_mma, cudaFuncAttributeMaxDynamicSharedMemorySize,
                             smem_bytes);
        attr_set = true;
    }

    collapse_all<<<(KDIM * NOUT + CTPB - 1) / CTPB, CTPB>>>(
        W0, b0, W1, b1, W2, b2, W3, b3, W4, b4,
        W5, b5, W6, b6, W7, b7, W8, b8);

    mlp_mma<<<BSZ / ROWS_PER_BLOCK, MTPB, smem_bytes>>>(x, out);   // 512 blocks
}